// round 1
// baseline (speedup 1.0000x reference)
#include <cuda_runtime.h>
#include <math.h>

#define T_   1024
#define CV_  8
#define DIM_ 2048
#define NH_  32
#define HD_  64
#define W_   8
#define BMM_ 2048   // NH*HD

// Scratch (device globals: no allocation allowed in kernel_launch)
__device__ float g_q[T_ * BMM_];            // 8 MB
__device__ float g_k[T_ * CV_ * BMM_];      // 64 MB
__device__ float g_v[T_ * CV_ * BMM_];      // 64 MB
__device__ float g_att[T_ * BMM_];          // 8 MB

// ---------------------------------------------------------------------------
// GEMM: C[M,N] = A[M,K] * B[N,K]^T   (both row-major, K contiguous)
// 128x128 block tile, BK=16, 8x8 per-thread micro-tile, 256 threads.
// Register-staged prefetch of the next K-tile overlaps LDG with FFMA.
// Requires M%128==0, N%128==0, K%16==0 (true for all 4 calls).
// ---------------------------------------------------------------------------
__global__ void __launch_bounds__(256, 2)
gemm_abt_kernel(const float* __restrict__ A, const float* __restrict__ Bm,
                float* __restrict__ C, int M, int N, int K) {
    __shared__ float As[16][128 + 4];   // +4 pad: bank spread, keeps 16B align
    __shared__ float Bs[16][128 + 4];

    const int bm  = blockIdx.y * 128;
    const int bn  = blockIdx.x * 128;
    const int tid = threadIdx.x;
    const int tx  = tid & 15;       // micro-tile col group
    const int ty  = tid >> 4;       // micro-tile row group
    const int lr  = tid >> 2;       // load row 0..63
    const int lk  = (tid & 3) << 2; // load k offset 0,4,8,12

    const float* Ap = A  + (size_t)(bm + lr) * K + lk;
    const float* Bp = Bm + (size_t)(bn + lr) * K + lk;
    const size_t rstep = (size_t)64 * K;

    float acc[8][8];
#pragma unroll
    for (int i = 0; i < 8; i++)
#pragma unroll
        for (int j = 0; j < 8; j++) acc[i][j] = 0.f;

    // prefetch tile 0
    float4 pa0 = *(const float4*)Ap;
    float4 pa1 = *(const float4*)(Ap + rstep);
    float4 pb0 = *(const float4*)Bp;
    float4 pb1 = *(const float4*)(Bp + rstep);

    const int nk = K >> 4;
    for (int kt = 0; kt < nk; ++kt) {
        // commit staged tile to smem (transposed: [k][row])
        As[lk + 0][lr]      = pa0.x; As[lk + 1][lr]      = pa0.y;
        As[lk + 2][lr]      = pa0.z; As[lk + 3][lr]      = pa0.w;
        As[lk + 0][lr + 64] = pa1.x; As[lk + 1][lr + 64] = pa1.y;
        As[lk + 2][lr + 64] = pa1.z; As[lk + 3][lr + 64] = pa1.w;
        Bs[lk + 0][lr]      = pb0.x; Bs[lk + 1][lr]      = pb0.y;
        Bs[lk + 2][lr]      = pb0.z; Bs[lk + 3][lr]      = pb0.w;
        Bs[lk + 0][lr + 64] = pb1.x; Bs[lk + 1][lr + 64] = pb1.y;
        Bs[lk + 2][lr + 64] = pb1.z; Bs[lk + 3][lr + 64] = pb1.w;
        __syncthreads();

        // issue next tile's LDGs; they complete while we FFMA below
        if (kt + 1 < nk) {
            const float* An = Ap + (size_t)(kt + 1) * 16;
            const float* Bn = Bp + (size_t)(kt + 1) * 16;
            pa0 = *(const float4*)An;
            pa1 = *(const float4*)(An + rstep);
            pb0 = *(const float4*)Bn;
            pb1 = *(const float4*)(Bn + rstep);
        }

#pragma unroll
        for (int k = 0; k < 16; ++k) {
            float af[8], bf[8];
            *(float4*)&af[0] = *(const float4*)&As[k][ty * 8];
            *(float4*)&af[4] = *(const float4*)&As[k][ty * 8 + 4];
            *(float4*)&bf[0] = *(const float4*)&Bs[k][tx * 8];
            *(float4*)&bf[4] = *(const float4*)&Bs[k][tx * 8 + 4];
#pragma unroll
            for (int i = 0; i < 8; i++)
#pragma unroll
                for (int j = 0; j < 8; j++)
                    acc[i][j] = fmaf(af[i], bf[j], acc[i][j]);
        }
        __syncthreads();
    }

#pragma unroll
    for (int i = 0; i < 8; i++) {
        float* Cp = C + (size_t)(bm + ty * 8 + i) * N + bn + tx * 8;
        *(float4*)Cp       = make_float4(acc[i][0], acc[i][1], acc[i][2], acc[i][3]);
        *(float4*)(Cp + 4) = make_float4(acc[i][4], acc[i][5], acc[i][6], acc[i][7]);
    }
}

// ---------------------------------------------------------------------------
// Windowed attention over 64 keys = (w in 0..7) x (cv in 0..7).
// Key/value row for (t, w, cv) is p = t + w - 7; p < 0 => zero-padded
// (score 0 participates in the softmax; v contribution is zero).
// RoPE is skipped: q and k share the same per-t rotation, which preserves
// the score dot products exactly; v is unrotated in the reference.
// One 64-thread block per (t, head).
// ---------------------------------------------------------------------------
__global__ void __launch_bounds__(64)
attn_kernel(const float* __restrict__ q, const float* __restrict__ k,
            const float* __restrict__ v, float* __restrict__ out) {
    const int t   = blockIdx.x;
    const int h   = blockIdx.y;
    const int tid = threadIdx.x;   // 0..63

    __shared__ float qs[64];
    __shared__ float sc[64];
    __shared__ float at[64];

    qs[tid] = q[(size_t)t * BMM_ + h * 64 + tid];
    __syncthreads();

    // thread = one key
    const int w  = tid >> 3;
    const int cv = tid & 7;
    const int p  = t + w - 7;
    float s = 0.f;
    if (p >= 0) {
        const float* kr = k + (size_t)(p * CV_ + cv) * BMM_ + h * 64;
#pragma unroll
        for (int d = 0; d < 64; d++) s = fmaf(qs[d], kr[d], s);
        s *= 0.125f;    // 1/sqrt(64)
    }
    sc[tid] = s;
    __syncthreads();

    float mx = -1e30f;
#pragma unroll
    for (int i = 0; i < 64; i++) mx = fmaxf(mx, sc[i]);
    float sum = 0.f;
#pragma unroll
    for (int i = 0; i < 64; i++) sum += expf(sc[i] - mx);
    at[tid] = expf(s - mx) / sum;
    __syncthreads();

    // thread = one output dim
    float acc = 0.f;
#pragma unroll
    for (int j = 0; j < 64; j++) {
        const int pj = t + (j >> 3) - 7;
        if (pj >= 0)
            acc = fmaf(at[j],
                       v[(size_t)(pj * CV_ + (j & 7)) * BMM_ + h * 64 + tid],
                       acc);
    }
    out[(size_t)t * BMM_ + h * 64 + tid] = acc;
}

// ---------------------------------------------------------------------------
extern "C" void kernel_launch(void* const* d_in, const int* in_sizes, int n_in,
                              void* d_out, int out_size) {
    const float* x     = (const float*)d_in[0];   // (1,1024,2048)
    const float* chars = (const float*)d_in[1];   // (1,1024,8,2048)
    const float* wq    = (const float*)d_in[2];   // (2048,2048)
    const float* wk    = (const float*)d_in[3];
    const float* wv    = (const float*)d_in[4];
    const float* wo    = (const float*)d_in[5];
    float* out = (float*)d_out;                   // (1,1024,2048)

    float *q, *k, *v, *att;
    cudaGetSymbolAddress((void**)&q,   g_q);
    cudaGetSymbolAddress((void**)&k,   g_k);
    cudaGetSymbolAddress((void**)&v,   g_v);
    cudaGetSymbolAddress((void**)&att, g_att);

    const dim3 thr(256);
    // Q = x @ wq^T : (1024 x 2048) = (1024 x 2048)(2048 x 2048)^T
    gemm_abt_kernel<<<dim3(BMM_ / 128, T_ / 128), thr>>>(x, wq, q, T_, BMM_, DIM_);
    // K = chars @ wk^T : (8192 x 2048)
    gemm_abt_kernel<<<dim3(BMM_ / 128, (T_ * CV_) / 128), thr>>>(chars, wk, k, T_ * CV_, BMM_, DIM_);
    // V = chars @ wv^T
    gemm_abt_kernel<<<dim3(BMM_ / 128, (T_ * CV_) / 128), thr>>>(chars, wv, v, T_ * CV_, BMM_, DIM_);
    // windowed attention
    attn_kernel<<<dim3(T_, NH_), dim3(64)>>>(q, k, v, att);
    // out = att @ wo^T : (1024 x 2048)
    gemm_abt_kernel<<<dim3(DIM_ / 128, T_ / 128), thr>>>(att, wo, out, T_, DIM_, BMM_);
}

// round 3
// speedup vs baseline: 2.0050x; 2.0050x over previous
#include <cuda_runtime.h>
#include <cuda_bf16.h>
#include <cstdint>
#include <math.h>

#define T_   1024
#define CV_  8
#define DIM_ 2048
#define NH_  32
#define BMM_ 2048   // NH*HD

// Scratch (device globals: no allocation allowed)
__device__ float g_q[T_ * BMM_];            // 8 MB
__device__ float g_k[T_ * CV_ * BMM_];      // 64 MB
__device__ float g_v[T_ * CV_ * BMM_];      // 64 MB
__device__ float g_att[T_ * BMM_];          // 8 MB

// ---------------------------------------------------------------------------
// GEMM C[M,N] = A[M,K] * B[N,K]^T via mma.sync bf16 with 2-way split (bf16x3).
// Tile 128x128x32, 8 warps (2x4), warp tile 64x32, double-buffered smem.
// ---------------------------------------------------------------------------
#define BM 128
#define BN 128
#define BK 32
#define AH_OFF 0
#define AL_OFF 8192
#define BH_OFF 16384
#define BL_OFF 24576
#define STAGE  32768
#define GEMM_SMEM (2 * STAGE)   // 64 KB

// SW64 swizzle: XOR 16B-chunk index (bits 4-5) with row bits (bits 7-8).
__device__ __forceinline__ uint32_t swz64(uint32_t o) { return o ^ ((o >> 3) & 0x30); }

__device__ __forceinline__ uint32_t smem_u32(const void* p) {
    uint32_t a;
    asm("{ .reg .u64 t; cvta.to.shared.u64 t, %1; cvt.u32.u64 %0, t; }"
        : "=r"(a) : "l"(p));
    return a;
}
__device__ __forceinline__ void ldsm4(uint32_t& r0, uint32_t& r1, uint32_t& r2,
                                      uint32_t& r3, uint32_t a) {
    asm volatile("ldmatrix.sync.aligned.m8n8.x4.shared.b16 {%0,%1,%2,%3}, [%4];"
                 : "=r"(r0), "=r"(r1), "=r"(r2), "=r"(r3) : "r"(a));
}
__device__ __forceinline__ void mma16816(float* c, const uint32_t* a, const uint32_t* b) {
    asm volatile("mma.sync.aligned.m16n8k16.row.col.f32.bf16.bf16.f32 "
                 "{%0,%1,%2,%3}, {%4,%5,%6,%7}, {%8,%9}, {%0,%1,%2,%3};"
                 : "+f"(c[0]), "+f"(c[1]), "+f"(c[2]), "+f"(c[3])
                 : "r"(a[0]), "r"(a[1]), "r"(a[2]), "r"(a[3]), "r"(b[0]), "r"(b[1]));
}
__device__ __forceinline__ uint32_t pack_hi2(float x, float y, float& lx, float& ly) {
    __nv_bfloat16 hx = __float2bfloat16_rn(x), hy = __float2bfloat16_rn(y);
    lx = x - __bfloat162float(hx);
    ly = y - __bfloat162float(hy);
    __nv_bfloat162 h; h.x = hx; h.y = hy;
    return *reinterpret_cast<uint32_t*>(&h);
}
__device__ __forceinline__ uint32_t pack2(float x, float y) {
    __nv_bfloat162 h;
    h.x = __float2bfloat16_rn(x); h.y = __float2bfloat16_rn(y);
    return *reinterpret_cast<uint32_t*>(&h);
}

// Split an 8-float row chunk into bf16 hi/lo 16B vectors and store (swizzled).
__device__ __forceinline__ void cvt_sts_one(float4 f0, float4 f1, char* base_h,
                                            char* base_l, uint32_t off) {
    float l0, l1, l2, l3, l4, l5, l6, l7;
    uint4 hv;
    hv.x = pack_hi2(f0.x, f0.y, l0, l1);
    hv.y = pack_hi2(f0.z, f0.w, l2, l3);
    hv.z = pack_hi2(f1.x, f1.y, l4, l5);
    hv.w = pack_hi2(f1.z, f1.w, l6, l7);
    uint4 lv;
    lv.x = pack2(l0, l1); lv.y = pack2(l2, l3);
    lv.z = pack2(l4, l5); lv.w = pack2(l6, l7);
    *(uint4*)(base_h + off) = hv;
    *(uint4*)(base_l + off) = lv;
}

__global__ void __launch_bounds__(256, 1)
gemm_tc(const float* __restrict__ A, const float* __restrict__ Bm,
        float* __restrict__ C, int M, int N, int K) {
    extern __shared__ char sm[];
    const int tid  = threadIdx.x;
    const int lane = tid & 31;
    const int wid  = tid >> 5;
    const int wm   = wid >> 2;      // 0..1 : 64-row slice
    const int wn   = wid & 3;       // 0..3 : 32-col slice
    const int bm   = blockIdx.y * BM;
    const int bn   = blockIdx.x * BN;

    float acc[4][4][4];
#pragma unroll
    for (int i = 0; i < 4; i++)
#pragma unroll
        for (int j = 0; j < 4; j++)
#pragma unroll
            for (int r = 0; r < 4; r++) acc[i][j][r] = 0.f;

    const int NCHK = K / BK;
    const int arow = tid >> 2;       // 0..63 (+64 for second iteration)
    const int ac8  = tid & 3;        // 16B k-chunk (8 floats)

    float4 ra[4], rb[4];

    // ---- prologue: load chunk 0 into registers, convert, store stage 0
#pragma unroll
    for (int it = 0; it < 2; it++) {
        const int r = arow + it * 64;
        const float4* pa = (const float4*)(A + (size_t)(bm + r) * K + ac8 * 8);
        const float4* pb = (const float4*)(Bm + (size_t)(bn + r) * K + ac8 * 8);
        ra[it * 2] = pa[0]; ra[it * 2 + 1] = pa[1];
        rb[it * 2] = pb[0]; rb[it * 2 + 1] = pb[1];
    }
#pragma unroll
    for (int it = 0; it < 2; it++) {
        const int cid = it * 256 + tid;
        const uint32_t off = swz64(((uint32_t)(cid >> 2) << 6) + ((uint32_t)(cid & 3) << 4));
        cvt_sts_one(ra[it * 2], ra[it * 2 + 1], sm + AH_OFF, sm + AL_OFF, off);
        cvt_sts_one(rb[it * 2], rb[it * 2 + 1], sm + BH_OFF, sm + BL_OFF, off);
    }
    __syncthreads();

    const uint32_t sbase = smem_u32(sm);
    const int lrow = lane & 15;
    const uint32_t lcol = (uint32_t)(lane >> 4) << 4;   // 0 or 16 bytes

    for (int c = 0; c < NCHK; c++) {
        // prefetch next chunk (LDG overlaps the MMA block below)
        if (c + 1 < NCHK) {
            const int kc = (c + 1) * BK;
#pragma unroll
            for (int it = 0; it < 2; it++) {
                const int r = arow + it * 64;
                const float4* pa = (const float4*)(A + (size_t)(bm + r) * K + kc + ac8 * 8);
                const float4* pb = (const float4*)(Bm + (size_t)(bn + r) * K + kc + ac8 * 8);
                ra[it * 2] = pa[0]; ra[it * 2 + 1] = pa[1];
                rb[it * 2] = pb[0]; rb[it * 2 + 1] = pb[1];
            }
        }

        const uint32_t stg = sbase + (uint32_t)(c & 1) * STAGE;
#pragma unroll
        for (int ks = 0; ks < 2; ks++) {
            uint32_t ah[4][4], al[4][4], bh[4][2], bl[4][2];
#pragma unroll
            for (int mi = 0; mi < 4; mi++) {
                const uint32_t byte =
                    ((uint32_t)(wm * 64 + mi * 16 + lrow) << 6) + (uint32_t)ks * 32 + lcol;
                const uint32_t so = swz64(byte);
                ldsm4(ah[mi][0], ah[mi][1], ah[mi][2], ah[mi][3], stg + AH_OFF + so);
                ldsm4(al[mi][0], al[mi][1], al[mi][2], al[mi][3], stg + AL_OFF + so);
            }
#pragma unroll
            for (int nj = 0; nj < 2; nj++) {
                const uint32_t byte =
                    ((uint32_t)(wn * 32 + nj * 16 + lrow) << 6) + (uint32_t)ks * 32 + lcol;
                const uint32_t so = swz64(byte);
                uint32_t r0, r1, r2, r3;
                ldsm4(r0, r1, r2, r3, stg + BH_OFF + so);
                bh[nj * 2][0] = r0; bh[nj * 2 + 1][0] = r1;
                bh[nj * 2][1] = r2; bh[nj * 2 + 1][1] = r3;
                ldsm4(r0, r1, r2, r3, stg + BL_OFF + so);
                bl[nj * 2][0] = r0; bl[nj * 2 + 1][0] = r1;
                bl[nj * 2][1] = r2; bl[nj * 2 + 1][1] = r3;
            }
#pragma unroll
            for (int mi = 0; mi < 4; mi++)
#pragma unroll
                for (int ni = 0; ni < 4; ni++) {
                    mma16816(acc[mi][ni], ah[mi], bh[ni]);   // hi*hi
                    mma16816(acc[mi][ni], ah[mi], bl[ni]);   // hi*lo
                    mma16816(acc[mi][ni], al[mi], bh[ni]);   // lo*hi
                }
        }

        if (c + 1 < NCHK) {
            char* nxt = sm + (size_t)((c + 1) & 1) * STAGE;
#pragma unroll
            for (int it = 0; it < 2; it++) {
                const int cid = it * 256 + tid;
                const uint32_t off =
                    swz64(((uint32_t)(cid >> 2) << 6) + ((uint32_t)(cid & 3) << 4));
                cvt_sts_one(ra[it * 2], ra[it * 2 + 1], nxt + AH_OFF, nxt + AL_OFF, off);
                cvt_sts_one(rb[it * 2], rb[it * 2 + 1], nxt + BH_OFF, nxt + BL_OFF, off);
            }
        }
        __syncthreads();
    }

    // ---- epilogue: write fp32 accumulators
    const int gr = lane >> 2;
    const int gc = (lane & 3) << 1;
#pragma unroll
    for (int mi = 0; mi < 4; mi++)
#pragma unroll
        for (int ni = 0; ni < 4; ni++) {
            const int row = bm + wm * 64 + mi * 16 + gr;
            const int col = bn + wn * 32 + ni * 8 + gc;
            *(float2*)(C + (size_t)row * N + col) =
                make_float2(acc[mi][ni][0], acc[mi][ni][1]);
            *(float2*)(C + (size_t)(row + 8) * N + col) =
                make_float2(acc[mi][ni][2], acc[mi][ni][3]);
        }
}

// ---------------------------------------------------------------------------
// Windowed attention: 64 keys = (w 0..7) x (cv 0..7), p = t+w-7, zero-padded
// (score 0 in softmax, zero v). RoPE skipped: q and k share the same per-t
// rotation -> score dot products invariant; v unrotated in the reference.
// ---------------------------------------------------------------------------
__global__ void __launch_bounds__(64)
attn_kernel(const float* __restrict__ q, const float* __restrict__ k,
            const float* __restrict__ v, float* __restrict__ out) {
    const int t = blockIdx.x, h = blockIdx.y, tid = threadIdx.x;

    __shared__ float4 qs4[16];
    __shared__ float sc[64];
    __shared__ float at[64];

    if (tid < 16)
        qs4[tid] = *((const float4*)(q + (size_t)t * BMM_ + h * 64) + tid);
    __syncthreads();

    const int w = tid >> 3, cv = tid & 7, p = t + w - 7;
    float s = 0.f;
    if (p >= 0) {
        const float4* kr = (const float4*)(k + (size_t)(p * CV_ + cv) * BMM_ + h * 64);
#pragma unroll
        for (int i = 0; i < 16; i++) {
            float4 a = qs4[i], b = kr[i];
            s = fmaf(a.x, b.x, s); s = fmaf(a.y, b.y, s);
            s = fmaf(a.z, b.z, s); s = fmaf(a.w, b.w, s);
        }
        s *= 0.125f;   // 1/sqrt(64)
    }
    sc[tid] = s;
    __syncthreads();

    float mx = -1e30f;
#pragma unroll
    for (int i = 0; i < 64; i++) mx = fmaxf(mx, sc[i]);
    float sum = 0.f;
#pragma unroll
    for (int i = 0; i < 64; i++) sum += expf(sc[i] - mx);
    at[tid] = expf(s - mx) / sum;
    __syncthreads();

    float acc = 0.f;
#pragma unroll
    for (int j = 0; j < 64; j++) {
        const int pj = t + (j >> 3) - 7;
        if (pj >= 0)
            acc = fmaf(at[j],
                       v[(size_t)(pj * CV_ + (j & 7)) * BMM_ + h * 64 + tid],
                       acc);
    }
    out[(size_t)t * BMM_ + h * 64 + tid] = acc;
}

// ---------------------------------------------------------------------------
extern "C" void kernel_launch(void* const* d_in, const int* in_sizes, int n_in,
                              void* d_out, int out_size) {
    const float* x     = (const float*)d_in[0];
    const float* chars = (const float*)d_in[1];
    const float* wq    = (const float*)d_in[2];
    const float* wk    = (const float*)d_in[3];
    const float* wv    = (const float*)d_in[4];
    const float* wo    = (const float*)d_in[5];
    float* out = (float*)d_out;

    float *q, *k, *v, *att;
    cudaGetSymbolAddress((void**)&q,   g_q);
    cudaGetSymbolAddress((void**)&k,   g_k);
    cudaGetSymbolAddress((void**)&v,   g_v);
    cudaGetSymbolAddress((void**)&att, g_att);

    cudaFuncSetAttribute(gemm_tc, cudaFuncAttributeMaxDynamicSharedMemorySize, GEMM_SMEM);

    gemm_tc<<<dim3(BMM_ / BN, T_ / BM), 256, GEMM_SMEM>>>(x, wq, q, T_, BMM_, DIM_);
    gemm_tc<<<dim3(BMM_ / BN, (T_ * CV_) / BM), 256, GEMM_SMEM>>>(chars, wk, k, T_ * CV_, BMM_, DIM_);
    gemm_tc<<<dim3(BMM_ / BN, (T_ * CV_) / BM), 256, GEMM_SMEM>>>(chars, wv, v, T_ * CV_, BMM_, DIM_);
    attn_kernel<<<dim3(T_, NH_), dim3(64)>>>(q, k, v, att);
    gemm_tc<<<dim3(DIM_ / BN, T_ / BM), 256, GEMM_SMEM>>>(att, wo, out, T_, DIM_, BMM_);
}

// round 4
// speedup vs baseline: 2.0136x; 1.0043x over previous
#include <cuda_runtime.h>
#include <cuda_bf16.h>
#include <cstdint>
#include <math.h>

#define T_   1024
#define CV_  8
#define DIM_ 2048
#define NH_  32
#define BMM_ 2048   // NH*HD

// ---------------------------------------------------------------------------
// Scratch (device globals; no allocation allowed)
// ---------------------------------------------------------------------------
__device__ float g_q[T_ * BMM_];                         // 8 MB
__device__ float g_k[T_ * CV_ * BMM_];                   // 64 MB
__device__ float g_v[T_ * CV_ * BMM_];                   // 64 MB
__device__ __align__(16) __nv_bfloat16 g_xh[T_ * DIM_], g_xl[T_ * DIM_];
__device__ __align__(16) __nv_bfloat16 g_ch[T_ * CV_ * DIM_], g_cl[T_ * CV_ * DIM_];
__device__ __align__(16) __nv_bfloat16 g_wqh[BMM_ * DIM_], g_wql[BMM_ * DIM_];
__device__ __align__(16) __nv_bfloat16 g_wkh[BMM_ * DIM_], g_wkl[BMM_ * DIM_];
__device__ __align__(16) __nv_bfloat16 g_wvh[BMM_ * DIM_], g_wvl[BMM_ * DIM_];
__device__ __align__(16) __nv_bfloat16 g_woh[DIM_ * BMM_], g_wol[DIM_ * BMM_];
__device__ __align__(16) __nv_bfloat16 g_ah[T_ * BMM_],  g_al[T_ * BMM_];

// ---------------------------------------------------------------------------
// helpers
// ---------------------------------------------------------------------------
__device__ __forceinline__ uint32_t smem_u32(const void* p) {
    uint32_t a;
    asm("{ .reg .u64 t; cvta.to.shared.u64 t, %1; cvt.u32.u64 %0, t; }"
        : "=r"(a) : "l"(p));
    return a;
}
// 64B-row swizzle: XOR 16B-chunk bits [4:5] with row bits [7:8]
__device__ __forceinline__ uint32_t swz64(uint32_t o) { return o ^ ((o >> 3) & 0x30); }

__device__ __forceinline__ void ldsm4(uint32_t& r0, uint32_t& r1, uint32_t& r2,
                                      uint32_t& r3, uint32_t a) {
    asm volatile("ldmatrix.sync.aligned.m8n8.x4.shared.b16 {%0,%1,%2,%3}, [%4];"
                 : "=r"(r0), "=r"(r1), "=r"(r2), "=r"(r3) : "r"(a));
}
__device__ __forceinline__ void mma16816(float* c, const uint32_t* a, const uint32_t* b) {
    asm volatile("mma.sync.aligned.m16n8k16.row.col.f32.bf16.bf16.f32 "
                 "{%0,%1,%2,%3}, {%4,%5,%6,%7}, {%8,%9}, {%0,%1,%2,%3};"
                 : "+f"(c[0]), "+f"(c[1]), "+f"(c[2]), "+f"(c[3])
                 : "r"(a[0]), "r"(a[1]), "r"(a[2]), "r"(a[3]), "r"(b[0]), "r"(b[1]));
}
__device__ __forceinline__ void cp16(uint32_t saddr, const void* gaddr) {
    asm volatile("cp.async.cg.shared.global [%0], [%1], 16;"
                 :: "r"(saddr), "l"(gaddr) : "memory");
}
__device__ __forceinline__ void cp_commit() {
    asm volatile("cp.async.commit_group;" ::: "memory");
}
template <int N> __device__ __forceinline__ void cp_wait() {
    asm volatile("cp.async.wait_group %0;" :: "n"(N) : "memory");
}
__device__ __forceinline__ uint32_t pack_hi2(float x, float y, float& lx, float& ly) {
    __nv_bfloat16 hx = __float2bfloat16_rn(x), hy = __float2bfloat16_rn(y);
    lx = x - __bfloat162float(hx);
    ly = y - __bfloat162float(hy);
    __nv_bfloat162 h; h.x = hx; h.y = hy;
    return *reinterpret_cast<uint32_t*>(&h);
}
__device__ __forceinline__ uint32_t pack2(float x, float y) {
    __nv_bfloat162 h;
    h.x = __float2bfloat16_rn(x); h.y = __float2bfloat16_rn(y);
    return *reinterpret_cast<uint32_t*>(&h);
}

// ---------------------------------------------------------------------------
// fp32 -> bf16 hi/lo split (one pass over each input)
// ---------------------------------------------------------------------------
__global__ void __launch_bounds__(256)
cvt_split(const float4* __restrict__ src, uint2* __restrict__ h,
          uint2* __restrict__ l, int n4) {
    for (int i = blockIdx.x * blockDim.x + threadIdx.x; i < n4;
         i += gridDim.x * blockDim.x) {
        float4 f = src[i];
        float lx, ly, lz, lw;
        uint32_t h0 = pack_hi2(f.x, f.y, lx, ly);
        uint32_t h1 = pack_hi2(f.z, f.w, lz, lw);
        h[i] = make_uint2(h0, h1);
        l[i] = make_uint2(pack2(lx, ly), pack2(lz, lw));
    }
}

// ---------------------------------------------------------------------------
// GEMM C[M,N] = A[M,K]*B[N,K]^T, bf16x3 (hi*hi + hi*lo + lo*hi), fp32 acc.
// Tile 128x256x32, 8 warps (warp tile 64x64), 3-stage cp.async pipeline.
// ---------------------------------------------------------------------------
#define BM 128
#define BN 256
#define BK 32
#define AH_OFF 0
#define AL_OFF 8192
#define BH_OFF 16384
#define BL_OFF 32768
#define STAGE  49152
#define NSTAGE 3
#define GEMM_SMEM (NSTAGE * STAGE)   // 147456

__device__ __forceinline__ void load_stage(
    const __nv_bfloat16* __restrict__ Ah, const __nv_bfloat16* __restrict__ Al,
    const __nv_bfloat16* __restrict__ Bh, const __nv_bfloat16* __restrict__ Bl,
    int bm, int bn, int K, int kc, uint32_t stg, int tid) {
#pragma unroll
    for (int j = 0; j < 2; j++) {                 // A: 128 rows x 4 chunks (x2 h/l)
        int idx = j * 256 + tid;
        int r = idx >> 2, c = idx & 3;
        uint32_t so = swz64((uint32_t)(r * 64 + c * 16));
        size_t go = (size_t)(bm + r) * K + kc + c * 8;
        cp16(stg + AH_OFF + so, Ah + go);
        cp16(stg + AL_OFF + so, Al + go);
    }
#pragma unroll
    for (int j = 0; j < 4; j++) {                 // B: 256 rows x 4 chunks (x2 h/l)
        int idx = j * 256 + tid;
        int r = idx >> 2, c = idx & 3;
        uint32_t so = swz64((uint32_t)(r * 64 + c * 16));
        size_t go = (size_t)(bn + r) * K + kc + c * 8;
        cp16(stg + BH_OFF + so, Bh + go);
        cp16(stg + BL_OFF + so, Bl + go);
    }
}

__global__ void __launch_bounds__(256, 1)
gemm_bf16x3(const __nv_bfloat16* __restrict__ Ah, const __nv_bfloat16* __restrict__ Al,
            const __nv_bfloat16* __restrict__ Bh, const __nv_bfloat16* __restrict__ Bl,
            float* __restrict__ C, int M, int N, int K) {
    extern __shared__ char sm[];
    const uint32_t sb = smem_u32(sm);
    const int tid  = threadIdx.x;
    const int lane = tid & 31;
    const int wid  = tid >> 5;
    const int wm   = wid >> 2;   // 0..1  (64-row slice)
    const int wn   = wid & 3;    // 0..3  (64-col slice)
    const int bm   = blockIdx.y * BM;
    const int bn   = blockIdx.x * BN;

    float acc[4][8][4];
#pragma unroll
    for (int i = 0; i < 4; i++)
#pragma unroll
        for (int j = 0; j < 8; j++)
#pragma unroll
            for (int r = 0; r < 4; r++) acc[i][j][r] = 0.f;

    const int NCHK = K / BK;      // 64
    load_stage(Ah, Al, Bh, Bl, bm, bn, K, 0, sb, tid);            cp_commit();
    load_stage(Ah, Al, Bh, Bl, bm, bn, K, BK, sb + STAGE, tid);   cp_commit();

    const int lr   = (lane & 7) + ((lane >> 3) & 1) * 8;  // row within 16
    const int lc16 = lane >> 4;                           // 0/1 (16B chunk)

    for (int c = 0; c < NCHK; c++) {
        cp_wait<1>();
        __syncthreads();

        if (c + 2 < NCHK)
            load_stage(Ah, Al, Bh, Bl, bm, bn, K, (c + 2) * BK,
                       sb + (uint32_t)((c + 2) % NSTAGE) * STAGE, tid);
        cp_commit();

        const uint32_t stg = sb + (uint32_t)(c % NSTAGE) * STAGE;
#pragma unroll
        for (int ks = 0; ks < 2; ks++) {
            uint32_t ah[4][4], al[4][4];
#pragma unroll
            for (int mi = 0; mi < 4; mi++) {
                const int r = wm * 64 + mi * 16 + lr;
                const uint32_t so = swz64((uint32_t)(r * 64 + (ks * 2 + lc16) * 16));
                ldsm4(ah[mi][0], ah[mi][1], ah[mi][2], ah[mi][3], stg + AH_OFF + so);
                ldsm4(al[mi][0], al[mi][1], al[mi][2], al[mi][3], stg + AL_OFF + so);
            }
#pragma unroll
            for (int nj = 0; nj < 4; nj++) {
                const int r = wn * 64 + nj * 16 + lr;
                const uint32_t so = swz64((uint32_t)(r * 64 + (ks * 2 + lc16) * 16));
                uint32_t h0, h1, h2, h3, l0, l1, l2, l3;
                ldsm4(h0, h1, h2, h3, stg + BH_OFF + so);
                ldsm4(l0, l1, l2, l3, stg + BL_OFF + so);
                uint32_t b0h[2] = {h0, h2}, b1h[2] = {h1, h3};
                uint32_t b0l[2] = {l0, l2}, b1l[2] = {l1, l3};
#pragma unroll
                for (int mi = 0; mi < 4; mi++) {
                    mma16816(acc[mi][nj * 2],     ah[mi], b0h);
                    mma16816(acc[mi][nj * 2],     ah[mi], b0l);
                    mma16816(acc[mi][nj * 2],     al[mi], b0h);
                    mma16816(acc[mi][nj * 2 + 1], ah[mi], b1h);
                    mma16816(acc[mi][nj * 2 + 1], ah[mi], b1l);
                    mma16816(acc[mi][nj * 2 + 1], al[mi], b1h);
                }
            }
        }
    }

    const int gr = lane >> 2, gc = (lane & 3) << 1;
#pragma unroll
    for (int mi = 0; mi < 4; mi++)
#pragma unroll
        for (int nn = 0; nn < 8; nn++) {
            const int row = bm + wm * 64 + mi * 16 + gr;
            const int col = bn + wn * 64 + nn * 8 + gc;
            *(float2*)(C + (size_t)row * N + col) =
                make_float2(acc[mi][nn][0], acc[mi][nn][1]);
            *(float2*)(C + (size_t)(row + 8) * N + col) =
                make_float2(acc[mi][nn][2], acc[mi][nn][3]);
        }
}

// ---------------------------------------------------------------------------
// Windowed attention. 64 keys/query: (w 0..7) x (cv 0..7), p = t+w-7;
// p<0 rows are zero-padded (score 0 in softmax, zero v). RoPE drops out:
// q and k share the same per-t rotation -> dot products invariant; v unrotated.
// 256 threads = 4 (t,h) units of 64 threads. Output split to bf16 hi/lo for
// the O-GEMM.
// ---------------------------------------------------------------------------
__global__ void __launch_bounds__(256)
attn_kernel(const float* __restrict__ q, const float* __restrict__ k,
            const float* __restrict__ v,
            __nv_bfloat16* __restrict__ oh, __nv_bfloat16* __restrict__ ol) {
    const int t    = blockIdx.x;
    const int u    = threadIdx.x >> 6;          // unit 0..3
    const int ut   = threadIdx.x & 63;
    const int h    = blockIdx.y * 4 + u;
    const int lane = threadIdx.x & 31;
    const int wid  = threadIdx.x >> 5;          // 0..7

    __shared__ float4 qs4[4][16];
    __shared__ float  at[256];
    __shared__ float  wmax[8], wsum[8];

    if (ut < 16)
        qs4[u][ut] = ((const float4*)(q + (size_t)t * BMM_ + h * 64))[ut];
    __syncthreads();

    const int w = ut >> 3, cv = ut & 7, p = t + w - 7;
    float s = 0.f;
    if (p >= 0) {
        const float4* kr = (const float4*)(k + (size_t)(p * CV_ + cv) * BMM_ + h * 64);
#pragma unroll
        for (int i = 0; i < 16; i++) {
            float4 a = qs4[u][i], b = kr[i];
            s = fmaf(a.x, b.x, s); s = fmaf(a.y, b.y, s);
            s = fmaf(a.z, b.z, s); s = fmaf(a.w, b.w, s);
        }
        s *= 0.125f;   // 1/sqrt(64)
    }

    float m = s;
#pragma unroll
    for (int o = 16; o; o >>= 1) m = fmaxf(m, __shfl_xor_sync(0xffffffffu, m, o));
    if (lane == 0) wmax[wid] = m;
    __syncthreads();
    const float mx = fmaxf(wmax[u * 2], wmax[u * 2 + 1]);

    const float e = expf(s - mx);
    float sum = e;
#pragma unroll
    for (int o = 16; o; o >>= 1) sum += __shfl_xor_sync(0xffffffffu, sum, o);
    if (lane == 0) wsum[wid] = sum;
    __syncthreads();
    at[threadIdx.x] = e / (wsum[u * 2] + wsum[u * 2 + 1]);
    __syncthreads();

    float acc = 0.f;
#pragma unroll
    for (int j = 0; j < 64; j++) {
        const int pj = t + (j >> 3) - 7;
        if (pj >= 0)
            acc = fmaf(at[u * 64 + j],
                       v[(size_t)(pj * CV_ + (j & 7)) * BMM_ + h * 64 + ut],
                       acc);
    }
    const size_t oidx = (size_t)t * BMM_ + h * 64 + ut;
    __nv_bfloat16 hh = __float2bfloat16_rn(acc);
    oh[oidx] = hh;
    ol[oidx] = __float2bfloat16_rn(acc - __bfloat162float(hh));
}

// ---------------------------------------------------------------------------
extern "C" void kernel_launch(void* const* d_in, const int* in_sizes, int n_in,
                              void* d_out, int out_size) {
    const float* x     = (const float*)d_in[0];
    const float* chars = (const float*)d_in[1];
    const float* wq    = (const float*)d_in[2];
    const float* wk    = (const float*)d_in[3];
    const float* wv    = (const float*)d_in[4];
    const float* wo    = (const float*)d_in[5];
    float* out = (float*)d_out;

    float *q, *k, *v;
    __nv_bfloat16 *xh, *xl, *ch, *cl, *wqh, *wql, *wkh, *wkl, *wvh, *wvl, *woh, *wol, *ah, *al;
    cudaGetSymbolAddress((void**)&q,   g_q);
    cudaGetSymbolAddress((void**)&k,   g_k);
    cudaGetSymbolAddress((void**)&v,   g_v);
    cudaGetSymbolAddress((void**)&xh,  g_xh);  cudaGetSymbolAddress((void**)&xl,  g_xl);
    cudaGetSymbolAddress((void**)&ch,  g_ch);  cudaGetSymbolAddress((void**)&cl,  g_cl);
    cudaGetSymbolAddress((void**)&wqh, g_wqh); cudaGetSymbolAddress((void**)&wql, g_wql);
    cudaGetSymbolAddress((void**)&wkh, g_wkh); cudaGetSymbolAddress((void**)&wkl, g_wkl);
    cudaGetSymbolAddress((void**)&wvh, g_wvh); cudaGetSymbolAddress((void**)&wvl, g_wvl);
    cudaGetSymbolAddress((void**)&woh, g_woh); cudaGetSymbolAddress((void**)&wol, g_wol);
    cudaGetSymbolAddress((void**)&ah,  g_ah);  cudaGetSymbolAddress((void**)&al,  g_al);

    cudaFuncSetAttribute(gemm_bf16x3, cudaFuncAttributeMaxDynamicSharedMemorySize,
                         GEMM_SMEM);

    auto cvt = [](const float* s, __nv_bfloat16* h, __nv_bfloat16* l, int n) {
        int n4 = n / 4;
        int grid = (n4 + 255) / 256;
        if (grid > 8192) grid = 8192;
        cvt_split<<<grid, 256>>>((const float4*)s, (uint2*)h, (uint2*)l, n4);
    };
    cvt(x,     xh,  xl,  T_ * DIM_);
    cvt(chars, ch,  cl,  T_ * CV_ * DIM_);
    cvt(wq,    wqh, wql, BMM_ * DIM_);
    cvt(wk,    wkh, wkl, BMM_ * DIM_);
    cvt(wv,    wvh, wvl, BMM_ * DIM_);
    cvt(wo,    woh, wol, DIM_ * BMM_);

    gemm_bf16x3<<<dim3(BMM_ / BN, T_ / BM), 256, GEMM_SMEM>>>(
        xh, xl, wqh, wql, q, T_, BMM_, DIM_);
    gemm_bf16x3<<<dim3(BMM_ / BN, (T_ * CV_) / BM), 256, GEMM_SMEM>>>(
        ch, cl, wkh, wkl, k, T_ * CV_, BMM_, DIM_);
    gemm_bf16x3<<<dim3(BMM_ / BN, (T_ * CV_) / BM), 256, GEMM_SMEM>>>(
        ch, cl, wvh, wvl, v, T_ * CV_, BMM_, DIM_);
    attn_kernel<<<dim3(T_, NH_ / 4), 256>>>(q, k, v, ah, al);
    gemm_bf16x3<<<dim3(DIM_ / BN, T_ / BM), 256, GEMM_SMEM>>>(
        ah, al, woh, wol, out, T_, DIM_, BMM_);
}